// round 1
// baseline (speedup 1.0000x reference)
#include <cuda_runtime.h>
#include <cuda_bf16.h>
#include <math.h>

// Problem dims (fixed per reference)
#define T_DIM 256
#define B_DIM 256
#define V_DIM 512
#define H_DIM 1024
#define M_ALL (T_DIM * B_DIM)      // 65536
#define BH    (B_DIM * H_DIM)      // 262144
#define TBV   (T_DIM * B_DIM * V_DIM) // 33554432

// Scratch: __device__ globals (allocation-free rule)
__device__ float g_xh[(size_t)T_DIM * B_DIM * H_DIM]; // 256 MB
__device__ float g_hs[(size_t)T_DIM * B_DIM * H_DIM]; // 256 MB

// ---------------------------------------------------------------------------
// Classic fp32 SGEMM: C[M,N] = A[M,K] @ B[K,N] + bias[N]
// BM=128, BN=128, BK=8, 256 threads, 8x8 per thread.
// Requires M%128==0, N%128==0, K%8==0 (true for all our shapes).
// ---------------------------------------------------------------------------
__global__ void __launch_bounds__(256)
sgemm_bias_kernel(const float* __restrict__ A, const float* __restrict__ B,
                  const float* __restrict__ bias, float* __restrict__ C,
                  int M, int N, int K)
{
    constexpr int BM = 128, BN = 128, BK = 8, TM = 8, TN = 8;
    __shared__ float As[BK][BM];
    __shared__ float Bs[BK][BN];

    const int tid = threadIdx.x;
    const int bm = blockIdx.y * BM;
    const int bn = blockIdx.x * BN;

    const int tx = tid % (BN / TN);   // 0..15
    const int ty = tid / (BN / TN);   // 0..15
    const int row0 = ty * TM;
    const int col0 = tx * TN;

    // A tile loads: 128x8 = 256 float4 (2 per row), one per thread
    const int aRow  = tid / (BK / 4);         // 0..127
    const int aCol4 = (tid % (BK / 4)) * 4;   // 0 or 4
    // B tile loads: 8x128 = 256 float4 (32 per row), one per thread
    const int bRow  = tid / (BN / 4);         // 0..7
    const int bCol4 = (tid % (BN / 4)) * 4;   // 0..124

    const float* Aptr = A + (size_t)bm * K;
    const float* Bptr = B + bn;

    float acc[TM][TN];
#pragma unroll
    for (int i = 0; i < TM; i++)
#pragma unroll
        for (int j = 0; j < TN; j++) acc[i][j] = 0.0f;

    for (int k0 = 0; k0 < K; k0 += BK) {
        float4 a4 = *(const float4*)(Aptr + (size_t)aRow * K + k0 + aCol4);
        As[aCol4 + 0][aRow] = a4.x;
        As[aCol4 + 1][aRow] = a4.y;
        As[aCol4 + 2][aRow] = a4.z;
        As[aCol4 + 3][aRow] = a4.w;
        *(float4*)&Bs[bRow][bCol4] =
            *(const float4*)(Bptr + (size_t)(k0 + bRow) * N + bCol4);
        __syncthreads();

#pragma unroll
        for (int k = 0; k < BK; k++) {
            float ra[TM], rb[TN];
#pragma unroll
            for (int i = 0; i < TM; i++) ra[i] = As[k][row0 + i];
#pragma unroll
            for (int j = 0; j < TN; j++) rb[j] = Bs[k][col0 + j];
#pragma unroll
            for (int i = 0; i < TM; i++)
#pragma unroll
                for (int j = 0; j < TN; j++)
                    acc[i][j] = fmaf(ra[i], rb[j], acc[i][j]);
        }
        __syncthreads();
    }

    // Epilogue: add bias, vectorized store
#pragma unroll
    for (int i = 0; i < TM; i++) {
        const size_t gr = (size_t)(bm + row0 + i);
#pragma unroll
        for (int j = 0; j < TN; j += 4) {
            const int gc = bn + col0 + j;
            float4 bv = *(const float4*)(bias + gc);
            float4 v;
            v.x = acc[i][j + 0] + bv.x;
            v.y = acc[i][j + 1] + bv.y;
            v.z = acc[i][j + 2] + bv.z;
            v.w = acc[i][j + 3] + bv.w;
            *(float4*)(C + gr * N + gc) = v;
        }
    }
}

// ---------------------------------------------------------------------------
// Recurrence step: h_out = tanh(xh_t + h_prev @ W_hh)
// M=256 (batch), N=1024, K=1024. BM=32, BN=64, BK=32, 256 threads, 2x4/thread.
// grid = (1024/64, 256/32) = (16, 8) = 128 blocks -> all SMs get work.
// W_hh (4 MB) stays L2-resident across the 256 steps.
// ---------------------------------------------------------------------------
__global__ void __launch_bounds__(256)
rnn_step_kernel(const float* __restrict__ h_prev,  // [256,1024]
                const float* __restrict__ W,       // [1024,1024]
                const float* __restrict__ xh_t,    // [256,1024]
                float* __restrict__ h_out)         // [256,1024]
{
    constexpr int BM = 32, BN = 64, BK = 32;
    __shared__ float Hs[BK][BM + 1];  // +1 pad: conflict-free transposed stores
    __shared__ float Ws[BK][BN];

    const int tid = threadIdx.x;
    const int bm = blockIdx.y * BM;
    const int bn = blockIdx.x * BN;

    const int tx = tid % 16;       // 16 cols of threads
    const int ty = tid / 16;       // 16 rows of threads
    const int row0 = ty * 2;
    const int col0 = tx * 4;

    // H tile: 32x32 floats = 256 float4 (one per thread)
    const int aRow = tid / 8;         // 0..31
    const int aCol = (tid % 8) * 4;   // 0..28
    // W tile: 32x64 floats = 512 float4 (two per thread)
    const int wRow = tid / 16;        // 0..15
    const int wCol = (tid % 16) * 4;  // 0..60

    float acc[2][4] = {{0.f, 0.f, 0.f, 0.f}, {0.f, 0.f, 0.f, 0.f}};

    for (int k0 = 0; k0 < H_DIM; k0 += BK) {
        float4 a4 = *(const float4*)(h_prev + (size_t)(bm + aRow) * H_DIM + k0 + aCol);
        Hs[aCol + 0][aRow] = a4.x;
        Hs[aCol + 1][aRow] = a4.y;
        Hs[aCol + 2][aRow] = a4.z;
        Hs[aCol + 3][aRow] = a4.w;
        *(float4*)&Ws[wRow][wCol] =
            *(const float4*)(W + (size_t)(k0 + wRow) * H_DIM + bn + wCol);
        *(float4*)&Ws[wRow + 16][wCol] =
            *(const float4*)(W + (size_t)(k0 + wRow + 16) * H_DIM + bn + wCol);
        __syncthreads();

#pragma unroll
        for (int k = 0; k < BK; k++) {
            const float a0 = Hs[k][row0 + 0];
            const float a1 = Hs[k][row0 + 1];
            const float4 b = *(const float4*)&Ws[k][col0];
            acc[0][0] = fmaf(a0, b.x, acc[0][0]);
            acc[0][1] = fmaf(a0, b.y, acc[0][1]);
            acc[0][2] = fmaf(a0, b.z, acc[0][2]);
            acc[0][3] = fmaf(a0, b.w, acc[0][3]);
            acc[1][0] = fmaf(a1, b.x, acc[1][0]);
            acc[1][1] = fmaf(a1, b.y, acc[1][1]);
            acc[1][2] = fmaf(a1, b.z, acc[1][2]);
            acc[1][3] = fmaf(a1, b.w, acc[1][3]);
        }
        __syncthreads();
    }

#pragma unroll
    for (int i = 0; i < 2; i++) {
        const size_t gr = (size_t)(bm + row0 + i);
        const int gc = bn + col0;
        float4 x = *(const float4*)(xh_t + gr * H_DIM + gc);
        float4 o;
        o.x = tanhf(acc[i][0] + x.x);
        o.y = tanhf(acc[i][1] + x.y);
        o.z = tanhf(acc[i][2] + x.z);
        o.w = tanhf(acc[i][3] + x.w);
        *(float4*)(h_out + gr * H_DIM + gc) = o;
    }
}

// First step: h_0 = tanh(xh_0)   (h_{-1} = 0)
__global__ void __launch_bounds__(256)
tanh_kernel(const float* __restrict__ x, float* __restrict__ y)
{
    const size_t i = ((size_t)blockIdx.x * blockDim.x + threadIdx.x) * 4;
    float4 v = *(const float4*)(x + i);
    v.x = tanhf(v.x);
    v.y = tanhf(v.y);
    v.z = tanhf(v.z);
    v.w = tanhf(v.w);
    *(float4*)(y + i) = v;
}

__global__ void __launch_bounds__(256)
copy_kernel(const float* __restrict__ src, float* __restrict__ dst)
{
    const size_t i = ((size_t)blockIdx.x * blockDim.x + threadIdx.x) * 4;
    *(float4*)(dst + i) = *(const float4*)(src + i);
}

// ---------------------------------------------------------------------------
extern "C" void kernel_launch(void* const* d_in, const int* in_sizes, int n_in,
                              void* d_out, int out_size)
{
    const float* inputs  = (const float*)d_in[0]; // [T,B,V]
    const float* W_xh    = (const float*)d_in[1]; // [V,H]
    const float* W_hh    = (const float*)d_in[2]; // [H,H]
    const float* b_h     = (const float*)d_in[3]; // [H]
    const float* W_dense = (const float*)d_in[4]; // [H,V]
    const float* b_dense = (const float*)d_in[5]; // [V]
    float* out = (float*)d_out;

    float* xh = nullptr;
    float* hs = nullptr;
    cudaGetSymbolAddress((void**)&xh, g_xh);
    cudaGetSymbolAddress((void**)&hs, g_hs);

    // 1) xh = inputs @ W_xh + b_h   : [65536,512] x [512,1024]
    {
        dim3 grid(H_DIM / 128, M_ALL / 128);
        sgemm_bias_kernel<<<grid, 256>>>(inputs, W_xh, b_h, xh,
                                         M_ALL, H_DIM, V_DIM);
    }

    // 2) Recurrence. h_0 = tanh(xh_0); h_t = tanh(xh_t + h_{t-1} @ W_hh)
    {
        tanh_kernel<<<BH / (256 * 4), 256>>>(xh, hs);
        dim3 grid(H_DIM / 64, B_DIM / 32); // (16, 8) = 128 blocks
        for (int t = 1; t < T_DIM; t++) {
            rnn_step_kernel<<<grid, 256>>>(hs + (size_t)(t - 1) * BH, W_hh,
                                           xh + (size_t)t * BH,
                                           hs + (size_t)t * BH);
        }
    }

    // 3) outputs = hs @ W_dense + b_dense : [65536,1024] x [1024,512]
    {
        dim3 grid(V_DIM / 128, M_ALL / 128);
        sgemm_bias_kernel<<<grid, 256>>>(hs, W_dense, b_dense, out,
                                         M_ALL, V_DIM, H_DIM);
    }

    // 4) state = h_{T-1}, appended after outputs
    if (out_size >= TBV + BH) {
        copy_kernel<<<BH / (256 * 4), 256>>>(hs + (size_t)(T_DIM - 1) * BH,
                                             out + TBV);
    }
}